// round 13
// baseline (speedup 1.0000x reference)
#include <cuda_runtime.h>
#include <cstdint>

// Problem constants: B=128, C=3, H=W=256, PROB=0.9, BRI=CON=SAT=0.2, CUT=0.25 -> CH=CW=64.
#define PROB_ 0.9f
static constexpr int B_     = 128;
static constexpr int H_     = 256;
static constexpr int W_     = 256;
static constexpr int CH_    = 64;
static constexpr int CW_    = 64;
static constexpr int PLANE  = H_ * W_;        // 65536 floats
static constexpr int PLANE4 = PLANE / 4;      // 16384 float4
static constexpr int CLUS   = 4;              // CTAs per batch (cluster)
static constexpr int NT     = 1024;           // threads per CTA
static constexpr int Q4     = PLANE4 / CLUS;  // 4096 float4 per channel slice (64 rows)
static constexpr int ITQ    = Q4 / NT;        // 4 float4 per thread per channel
static constexpr int SMEM_BYTES = 3 * Q4 * 16 + 64;  // 3 channel tiles + aux

__device__ __forceinline__ float4 rev4(float4 v) {
    float4 o; o.x = v.w; o.y = v.z; o.z = v.y; o.w = v.x; return o;
}

// Affine transform + cutout for one float4 (4 consecutive columns c0..c0+3).
__device__ __forceinline__ void xf4(
    float4 r, float4 g, float4 c, int c0, bool row_in, int l_,
    float A, float D, float E0, float E1, float E2,
    float4& oR, float4& oG, float4& oB)
{
    float gray; bool cut; int col;
    col = c0 + 0; cut = row_in && (col >= l_) && (col < l_ + CW_);
    gray = (r.x + g.x + c.x) * (1.0f / 3.0f);
    oR.x = cut ? 0.0f : fmaf(A, r.x, fmaf(D, gray, E0));
    oG.x = cut ? 0.0f : fmaf(A, g.x, fmaf(D, gray, E1));
    oB.x = cut ? 0.0f : fmaf(A, c.x, fmaf(D, gray, E2));

    col = c0 + 1; cut = row_in && (col >= l_) && (col < l_ + CW_);
    gray = (r.y + g.y + c.y) * (1.0f / 3.0f);
    oR.y = cut ? 0.0f : fmaf(A, r.y, fmaf(D, gray, E0));
    oG.y = cut ? 0.0f : fmaf(A, g.y, fmaf(D, gray, E1));
    oB.y = cut ? 0.0f : fmaf(A, c.y, fmaf(D, gray, E2));

    col = c0 + 2; cut = row_in && (col >= l_) && (col < l_ + CW_);
    gray = (r.z + g.z + c.z) * (1.0f / 3.0f);
    oR.z = cut ? 0.0f : fmaf(A, r.z, fmaf(D, gray, E0));
    oG.z = cut ? 0.0f : fmaf(A, g.z, fmaf(D, gray, E1));
    oB.z = cut ? 0.0f : fmaf(A, c.z, fmaf(D, gray, E2));

    col = c0 + 3; cut = row_in && (col >= l_) && (col < l_ + CW_);
    gray = (r.w + g.w + c.w) * (1.0f / 3.0f);
    oR.w = cut ? 0.0f : fmaf(A, r.w, fmaf(D, gray, E0));
    oG.w = cut ? 0.0f : fmaf(A, g.w, fmaf(D, gray, E1));
    oB.w = cut ? 0.0f : fmaf(A, c.w, fmaf(D, gray, E2));
}

// ---------------------------------------------------------------------------
// One 4-CTA cluster = one batch; each CTA owns 64 rows x 3 channels (192KB) in
// SMEM, read from DRAM exactly once (staged cp.async; reductions overlap the
// in-flight loads). Means exchanged via DSMEM.
//
// Phase 2 splits the slice:
//   rows 0-31:  transform IN PLACE in SMEM (mirror-pair per thread: each
//               thread owns cols (wg, 63-wg) of one row, so flip has no
//               cross-thread hazard), then 3x cp.async.bulk (TMA bulk store,
//               32KB each) -- issued early, drains asynchronously.
//   rows 32-63: classic register transform + STG.128 while the bulk stores
//               drain in the background (the R/W mixing the sync versions
//               never achieved).
//
// Algebra: out_ch = A*x0_ch + D*g0 + E_ch with A=s*b*c; D=(1-s)*b*c;
//   E_ch=(1-c)*(s*M_ch+(1-s)*Mbar), M_ch=b*mean(raw plane); flip preserves
//   means; cutout/apply are selects.
// ---------------------------------------------------------------------------
__global__ void __cluster_dims__(CLUS, 1, 1) __launch_bounds__(NT, 1)
aug_kernel(const float* __restrict__ img,
           const float* __restrict__ apply_u,
           const float* __restrict__ flip_u,
           const float* __restrict__ bri_u,
           const float* __restrict__ con_u,
           const float* __restrict__ sat_u,
           const int*   __restrict__ top_idx,
           const int*   __restrict__ left_idx,
           float* __restrict__ out)
{
    extern __shared__ float4 smem4[];                   // 3 * Q4 float4 tiles
    float* aux = reinterpret_cast<float*>(smem4 + 3 * Q4);

    const int tid  = threadIdx.x;
    const int b    = blockIdx.x >> 2;
    const int rank = blockIdx.x & 3;

    const size_t base4 = (size_t)b * 3 * PLANE4 + (size_t)rank * Q4;
    const float4* in0 = reinterpret_cast<const float4*>(img) + base4;
    const float4* in1 = in0 + PLANE4;
    const float4* in2 = in0 + 2 * PLANE4;
    float4* out0 = reinterpret_cast<float4*>(out) + base4;
    float4* out1 = out0 + PLANE4;
    float4* out2 = out0 + 2 * PLANE4;

    const bool apply = (__ldg(apply_u + b) < PROB_);
    if (!apply) {
        // Whole cluster takes this path (same batch) -> no barrier mismatch.
#pragma unroll
        for (int i = 0; i < ITQ; i++) {
            const int j = tid + i * NT;
            out0[j] = __ldg(in0 + j);
            out1[j] = __ldg(in1 + j);
            out2[j] = __ldg(in2 + j);
        }
        return;
    }

    if (tid < 3) aux[4 + tid] = 0.0f;

    // ---------------- Phase 1: staged GMEM -> SMEM + overlapped sums -------
    const uint32_t sbase = (uint32_t)__cvta_generic_to_shared(smem4);
#pragma unroll
    for (int ch = 0; ch < 3; ch++) {
        const float4* src = (ch == 0) ? in0 : (ch == 1) ? in1 : in2;
#pragma unroll
        for (int i = 0; i < ITQ; i++) {
            const int j = tid + i * NT;
            const uint32_t dst = sbase + (uint32_t)(ch * Q4 + j) * 16u;
            asm volatile("cp.async.cg.shared.global [%0], [%1], 16;\n"
                         :: "r"(dst), "l"(src + j));
        }
        asm volatile("cp.async.commit_group;\n");
    }

    float s0, s1, s2;
    {
        auto sum_ch = [&](int ch) -> float {
            float s = 0.0f;
#pragma unroll
            for (int i = 0; i < ITQ; i++) {
                const int j = tid + i * NT;
                float4 v = smem4[ch * Q4 + j];
                s += (v.x + v.y) + (v.z + v.w);
            }
            return s;
        };
        asm volatile("cp.async.wait_group 2;\n" ::: "memory");
        s0 = sum_ch(0);
        asm volatile("cp.async.wait_group 1;\n" ::: "memory");
        s1 = sum_ch(1);
        asm volatile("cp.async.wait_group 0;\n" ::: "memory");
        s2 = sum_ch(2);
    }

#pragma unroll
    for (int o = 16; o > 0; o >>= 1) {
        s0 += __shfl_xor_sync(0xFFFFFFFFu, s0, o);
        s1 += __shfl_xor_sync(0xFFFFFFFFu, s1, o);
        s2 += __shfl_xor_sync(0xFFFFFFFFu, s2, o);
    }
    __shared__ float smA[32], smB[32], smC[32];
    const int wid = tid >> 5;
    if ((tid & 31) == 0) { smA[wid] = s0; smB[wid] = s1; smC[wid] = s2; }
    __syncthreads();   // publishes SMEM tiles for cross-thread reads too
    if (tid < 32) {
        float a = smA[tid], d = smB[tid], e = smC[tid];
#pragma unroll
        for (int o = 16; o > 0; o >>= 1) {
            a += __shfl_xor_sync(0xFFFFFFFFu, a, o);
            d += __shfl_xor_sync(0xFFFFFFFFu, d, o);
            e += __shfl_xor_sync(0xFFFFFFFFu, e, o);
        }
        if (tid == 0) { aux[0] = a; aux[1] = d; aux[2] = e; }
    }
    __syncthreads();

    // ---------------- Cluster-wide sum exchange via DSMEM ------------------
    asm volatile("barrier.cluster.arrive.aligned;" ::: "memory");
    asm volatile("barrier.cluster.wait.aligned;" ::: "memory");

    if (tid < 12) {
        const int ch = tid % 3;
        const int r  = tid / 3;
        uint32_t la = (uint32_t)__cvta_generic_to_shared(&aux[ch]);
        uint32_t ra;
        asm volatile("mapa.shared::cluster.u32 %0, %1, %2;"
                     : "=r"(ra) : "r"(la), "r"(r));
        float v;
        asm volatile("ld.shared::cluster.f32 %0, [%1];" : "=f"(v) : "r"(ra));
        atomicAdd(&aux[4 + ch], v);
    }
    __syncthreads();
    asm volatile("barrier.cluster.arrive.aligned;" ::: "memory");

    // ---------------- Per-batch constants -----------------------------------
    const float bv = 0.8f + 0.4f * __ldg(bri_u + b);
    const float cv = 0.8f + 0.4f * __ldg(con_u + b);
    const float sv = 0.8f + 0.4f * __ldg(sat_u + b);

    const float inv = 1.0f / (float)PLANE;
    const float M0 = aux[4] * inv * bv;
    const float M1 = aux[5] * inv * bv;
    const float M2 = aux[6] * inv * bv;
    const float Mbar = (M0 + M1 + M2) * (1.0f / 3.0f);

    const float A  = sv * bv * cv;
    const float D  = (1.0f - sv) * bv * cv;
    const float k  = 1.0f - cv;
    const float os = 1.0f - sv;
    const float E0 = k * (sv * M0 + os * Mbar);
    const float E1 = k * (sv * M1 + os * Mbar);
    const float E2 = k * (sv * M2 + os * Mbar);

    const bool flip = (__ldg(flip_u + b) < 0.5f);
    const int  t_   = __ldg(top_idx + b);
    const int  l_   = __ldg(left_idx + b);

    // ---------------- Phase 2a: rows 0-31 in place + TMA bulk store --------
    {
        const int rr = tid >> 5;            // local row 0..31
        const int wg = tid & 31;            // left column group of the pair
        const int mg = 63 - wg;             // mirrored column group
        const int h  = rank * 64 + rr;
        const bool row_in = (h >= t_) && (h < t_ + CH_);
        const int jj = (rr << 6) + wg;
        const int mm = (rr << 6) + mg;

        float4 rj = smem4[jj],          gj = smem4[Q4 + jj], bj = smem4[2 * Q4 + jj];
        float4 rm = smem4[mm],          gm = smem4[Q4 + mm], bm = smem4[2 * Q4 + mm];

        float4 srj = flip ? rev4(rm) : rj;
        float4 sgj = flip ? rev4(gm) : gj;
        float4 sbj = flip ? rev4(bm) : bj;
        float4 srm = flip ? rev4(rj) : rm;
        float4 sgm = flip ? rev4(gj) : gm;
        float4 sbm = flip ? rev4(bj) : bm;

        float4 oR, oG, oB;
        xf4(srj, sgj, sbj, wg << 2, row_in, l_, A, D, E0, E1, E2, oR, oG, oB);
        smem4[jj] = oR; smem4[Q4 + jj] = oG; smem4[2 * Q4 + jj] = oB;
        xf4(srm, sgm, sbm, mg << 2, row_in, l_, A, D, E0, E1, E2, oR, oG, oB);
        smem4[mm] = oR; smem4[Q4 + mm] = oG; smem4[2 * Q4 + mm] = oB;
    }
    __syncthreads();

    if (tid == 0) {
        asm volatile("fence.proxy.async.shared::cta;" ::: "memory");
#pragma unroll
        for (int ch = 0; ch < 3; ch++) {
            float4* dst = (ch == 0) ? out0 : (ch == 1) ? out1 : out2;
            unsigned long long gaddr;
            asm volatile("cvta.to.global.u64 %0, %1;" : "=l"(gaddr) : "l"(dst));
            const uint32_t saddr = sbase + (uint32_t)(ch * Q4) * 16u;
            asm volatile("cp.async.bulk.global.shared::cta.bulk_group [%0], [%1], %2;\n"
                         :: "l"(gaddr), "r"(saddr), "r"(32768u));
        }
        asm volatile("cp.async.bulk.commit_group;\n" ::: "memory");
    }

    // ---------------- Phase 2b: rows 32-63 via registers + STG -------------
    // Overlaps the background drain of the bulk stores above.
#pragma unroll
    for (int i = 0; i < 2; i++) {
        const int j  = 2048 + tid + i * NT;  // f4 idx, rows 32..63
        const int rr = j >> 6;
        const int wg = j & 63;
        const int h  = rank * 64 + rr;
        const int sj = (rr << 6) + (flip ? (63 - wg) : wg);

        float4 r = smem4[sj];
        float4 g = smem4[Q4 + sj];
        float4 c = smem4[2 * Q4 + sj];
        if (flip) { r = rev4(r); g = rev4(g); c = rev4(c); }

        const bool row_in = (h >= t_) && (h < t_ + CH_);
        float4 oR, oG, oB;
        xf4(r, g, c, wg << 2, row_in, l_, A, D, E0, E1, E2, oR, oG, oB);

        out0[j] = oR;
        out1[j] = oG;
        out2[j] = oB;
    }

    // Hold SMEM/aux valid: siblings may still read our aux; bulk store still
    // reads rows 0-31 of our SMEM until the group drains.
    asm volatile("barrier.cluster.wait.aligned;" ::: "memory");
    if (tid == 0) {
        asm volatile("cp.async.bulk.wait_group 0;\n" ::: "memory");
    }
}

extern "C" void kernel_launch(void* const* d_in, const int* in_sizes, int n_in,
                              void* d_out, int out_size) {
    const float* images       = (const float*)d_in[0];
    const float* apply_u      = (const float*)d_in[1];
    const float* flip_u       = (const float*)d_in[2];
    const float* brightness_u = (const float*)d_in[3];
    const float* contrast_u   = (const float*)d_in[4];
    const float* saturation_u = (const float*)d_in[5];
    const int*   top_idx      = (const int*)d_in[6];
    const int*   left_idx     = (const int*)d_in[7];
    float* out = (float*)d_out;

    cudaFuncSetAttribute(aug_kernel,
                         cudaFuncAttributeMaxDynamicSharedMemorySize,
                         SMEM_BYTES);

    aug_kernel<<<B_ * CLUS, NT, SMEM_BYTES>>>(
        images, apply_u, flip_u, brightness_u, contrast_u, saturation_u,
        top_idx, left_idx, out);
}